// round 12
// baseline (speedup 1.0000x reference)
#include <cuda_runtime.h>
#include <cstdint>
#include <cstddef>

#define BATCH 1024
#define TSTEPS 512
#define DIN 14
#define HID 128
#define KSH 46                 // Whh rows in SMEM per k-half
#define KRH 18                 // Whh rows in registers per k-half
#define NTT_H 8192             // gemm_h tiles: (B*T)/64
#define GRIDX_H 74             // gemm_h grid.x

typedef unsigned long long u64;

// ---------------- device scratch ----------------
__device__ float g_Wr0[128 * 512];     // Whh0 reordered [k][n*4+g]
__device__ float g_Wr1[128 * 512];     // Whh1 reordered
__device__ float g_Wi0r[14 * 512];     // Wih0 reordered [k][n*4+g]
__device__ float g_Wi1r[128 * 512];    // Wih1 reordered
__device__ float g_b0r[512];           // (bih0+bhh0) reordered [n*4+g]
__device__ float g_b1r[512];
__device__ float g_xw[(size_t)BATCH * TSTEPS * 512];   // 1 GB; [b*T+t][512]
__device__ float g_h1[(size_t)TSTEPS * BATCH * HID];   // 256 MB; [t*B+b][128]
__device__ float g_last[BATCH * HID];
__device__ float g_mu[HID];
__device__ float g_rstd[HID];

// ---------------- helpers ----------------
__device__ __forceinline__ u64 pack2(float lo, float hi) {
    u64 r;
    asm("mov.b64 %0, {%1, %2};" : "=l"(r)
        : "r"(__float_as_uint(lo)), "r"(__float_as_uint(hi)));
    return r;
}
__device__ __forceinline__ void fma2(u64& d, u64 a, u64 b) {
    asm("fma.rn.f32x2 %0, %1, %2, %0;" : "+l"(d) : "l"(a), "l"(b));
}
__device__ __forceinline__ void add2(u64& d, u64 a) {
    asm("add.rn.f32x2 %0, %0, %1;" : "+l"(d) : "l"(a));
}
__device__ __forceinline__ void unpk(u64 v, float& lo, float& hi) {
    unsigned int l, h;
    asm("mov.b64 {%0, %1}, %2;" : "=r"(l), "=r"(h) : "l"(v));
    lo = __uint_as_float(l); hi = __uint_as_float(h);
}
__device__ __forceinline__ float sigf(float x) {
    return __fdividef(1.0f, 1.0f + __expf(-x));
}
__device__ __forceinline__ float tanhf_(float x) {
    return __fdividef(2.0f, 1.0f + __expf(-2.0f * x)) - 1.0f;
}

// ---------------- prep: reorder weights [k][n*4+g], fuse biases ----------------
__global__ void prep_kernel(const float* __restrict__ Wih0, const float* __restrict__ Whh0,
                            const float* __restrict__ bih0, const float* __restrict__ bhh0,
                            const float* __restrict__ Wih1, const float* __restrict__ Whh1,
                            const float* __restrict__ bih1, const float* __restrict__ bhh1) {
    int idx0 = blockIdx.x * blockDim.x + threadIdx.x;
    int stride = gridDim.x * blockDim.x;
    for (int i = idx0; i < 128 * 512; i += stride) {
        int k = i >> 9, j = i & 511, n = j >> 2, g = j & 3;
        g_Wr0[i]  = Whh0[(g * 128 + n) * 128 + k];
        g_Wr1[i]  = Whh1[(g * 128 + n) * 128 + k];
        g_Wi1r[i] = Wih1[(g * 128 + n) * 128 + k];
    }
    for (int i = idx0; i < 14 * 512; i += stride) {
        int k = i / 512, j = i % 512, n = j >> 2, g = j & 3;
        g_Wi0r[i] = Wih0[(g * 128 + n) * 14 + k];
    }
    for (int i = idx0; i < 512; i += stride) {
        int n = i >> 2, g = i & 3;
        g_b0r[i] = bih0[g * 128 + n] + bhh0[g * 128 + n];
        g_b1r[i] = bih1[g * 128 + n] + bhh1[g * 128 + n];
    }
}

// ---------------- gemm0: xw0[m][512] = x[m][14] @ Wi0r + b0, m = b*T+t ----------------
__global__ void __launch_bounds__(256, 1) gemm_x_kernel(
    const float* __restrict__ X, const float* __restrict__ Wr,
    const float* __restrict__ bias, float* __restrict__ XW)
{
    __shared__ float Wsh[14 * 512];
    __shared__ float xs[14 * 16];
    const int tid = threadIdx.x;
    const int n = tid & 127;
    const int half = tid >> 7;

    for (int i = tid; i < 14 * 128; i += 256)
        ((float4*)Wsh)[i] = ((const float4*)Wr)[i];
    float4 bv = ((const float4*)bias)[n];
    const u64 bif = pack2(bv.x, bv.y), bgo = pack2(bv.z, bv.w);

    const bool stager = tid < 112;
    const int sr = tid / 14, sk = tid - sr * 14;
    const size_t m0b = (size_t)blockIdx.x * 1024;
    float pv = stager ? X[(m0b + sr) * 14 + sk] : 0.0f;
    __syncthreads();

    const ulonglong2* Wsh_u2 = (const ulonglong2*)Wsh;
    const ulonglong2* xs_u2  = (const ulonglong2*)xs;
    u64* xs_u = (u64*)xs;
    float4* XW4 = (float4*)XW;

    for (int tile = 0; tile < 128; tile++) {
        if (stager) xs_u[sk * 8 + sr] = pack2(pv, pv);
        __syncthreads();
        if (tile < 127 && stager)
            pv = X[(m0b + (size_t)(tile + 1) * 8 + sr) * 14 + sk];

        u64 aif0 = bif, aif1 = bif, aif2 = bif, aif3 = bif;
        u64 ago0 = bgo, ago1 = bgo, ago2 = bgo, ago3 = bgo;
        #pragma unroll
        for (int k = 0; k < 14; k++) {
            ulonglong2 w   = Wsh_u2[k * 128 + n];
            ulonglong2 h01 = xs_u2[k * 4 + half * 2];
            ulonglong2 h23 = xs_u2[k * 4 + half * 2 + 1];
            fma2(aif0, w.x, h01.x); fma2(ago0, w.y, h01.x);
            fma2(aif1, w.x, h01.y); fma2(ago1, w.y, h01.y);
            fma2(aif2, w.x, h23.x); fma2(ago2, w.y, h23.x);
            fma2(aif3, w.x, h23.y); fma2(ago3, w.y, h23.y);
        }
        size_t m0 = m0b + (size_t)tile * 8 + half * 4;
        float a, b, c, d;
        unpk(aif0, a, b); unpk(ago0, c, d); XW4[(m0 + 0) * 128 + n] = make_float4(a, b, c, d);
        unpk(aif1, a, b); unpk(ago1, c, d); XW4[(m0 + 1) * 128 + n] = make_float4(a, b, c, d);
        unpk(aif2, a, b); unpk(ago2, c, d); XW4[(m0 + 2) * 128 + n] = make_float4(a, b, c, d);
        unpk(aif3, a, b); unpk(ago3, c, d); XW4[(m0 + 3) * 128 + n] = make_float4(a, b, c, d);
        __syncthreads();
    }
}

// ---------------- gemm1 v3: 64-row tiles, 16 rows per thread (fma-bound) ----------------
// xw1[(b*T+t)][512] = h1[(t*B+b)][128] @ Wi1r + b1.  grid (GRIDX_H, 2).
__global__ void __launch_bounds__(256, 1) gemm_h_kernel(
    const float* __restrict__ X, const float* __restrict__ Wr,
    const float* __restrict__ bias, float* __restrict__ XW)
{
    extern __shared__ float sm[];
    float* Wsh  = sm;                     // 128 k * 256 floats = 128KB (cls half)
    u64*  xsd_u = (u64*)(sm + 128 * 256); // 128 k * 64 rows dup u64 = 64KB
    const int tid = threadIdx.x;
    const int cls = blockIdx.y;
    const int nl = tid & 63;              // n-unit in half
    const int rg = tid >> 6;              // row group 0..3 (16 rows each)
    const int ng = cls * 64 + nl;

    for (int i = tid; i < 128 * 64; i += 256) {
        int k = i >> 6, j4 = i & 63;
        ((float4*)Wsh)[i] = ((const float4*)Wr)[k * 128 + cls * 64 + j4];
    }
    float4 bv = ((const float4*)bias)[ng];
    const u64 bif = pack2(bv.x, bv.y), bgo = pack2(bv.z, bv.w);

    // staging map: sr = row-in-tile (lane-contiguous), cq picks 32 k-values
    const int sr = tid & 63, cq = tid >> 6;
    const float4* X4 = (const float4*)X;
    const ulonglong2* Wsh_u2 = (const ulonglong2*)Wsh;
    const ulonglong2* xsd_u2 = (const ulonglong2*)xsd_u;
    float4* XW4 = (float4*)XW;

    int tile = blockIdx.x;
    float4 px[8];
    {
        size_t mr = (size_t)tile * 64 + sr;
        #pragma unroll
        for (int q = 0; q < 8; q++) px[q] = X4[mr * 32 + cq * 8 + q];
    }

    for (; tile < NTT_H; tile += GRIDX_H) {
        // stage duplicated inputs: xsd[k][sr] = (x,x).  k = cq*32 + 4q + j
        #pragma unroll
        for (int q = 0; q < 8; q++) {
            int kb = cq * 32 + 4 * q;
            xsd_u[(kb + 0) * 64 + sr] = pack2(px[q].x, px[q].x);
            xsd_u[(kb + 1) * 64 + sr] = pack2(px[q].y, px[q].y);
            xsd_u[(kb + 2) * 64 + sr] = pack2(px[q].z, px[q].z);
            xsd_u[(kb + 3) * 64 + sr] = pack2(px[q].w, px[q].w);
        }
        __syncthreads();

        int tn = tile + GRIDX_H;
        if (tn < NTT_H) {
            size_t mr = (size_t)tn * 64 + sr;
            #pragma unroll
            for (int q = 0; q < 8; q++) px[q] = X4[mr * 32 + cq * 8 + q];
        }

        u64 aif[16], ago[16];
        #pragma unroll
        for (int j = 0; j < 16; j++) { aif[j] = bif; ago[j] = bgo; }

        #pragma unroll 4
        for (int k = 0; k < 128; k++) {
            ulonglong2 w = Wsh_u2[k * 64 + nl];
            const ulonglong2* hp = xsd_u2 + k * 32 + rg * 8;
            #pragma unroll
            for (int j2 = 0; j2 < 8; j2++) {
                ulonglong2 h = hp[j2];
                fma2(aif[2 * j2],     w.x, h.x); fma2(ago[2 * j2],     w.y, h.x);
                fma2(aif[2 * j2 + 1], w.x, h.y); fma2(ago[2 * j2 + 1], w.y, h.y);
            }
        }

        // epilogue: 16 rows, scatter to [b*T+t] layout
        #pragma unroll
        for (int jj = 0; jj < 16; jj++) {
            int mh = tile * 64 + rg * 16 + jj;   // h1-order index = t*B + b
            int b_ = mh & 1023;
            int t_ = mh >> 10;
            float a, b, c, d;
            unpk(aif[jj], a, b); unpk(ago[jj], c, d);
            XW4[((size_t)b_ * TSTEPS + t_) * 128 + ng] = make_float4(a, b, c, d);
        }
        __syncthreads();
    }
}

// ---------------- recurrence v4: 256 threads, k-split (2 warps/SMSP) ----------------
// warps 0-3: k in [0,64); warps 4-7: k in [64,128). Partial gates merged via smem.
// LAYER 0: hout = g_h1 [t*B+b][128]   LAYER 1: hout = g_last [b][128]
template <int LAYER>
__global__ void __launch_bounds__(256, 1) rec_kernel(
    const float* __restrict__ xw,   // [b*T+t][512] gate seeds incl. bias
    const float* __restrict__ Wr,   // [128][512] reordered
    float* __restrict__ hout)
{
    extern __shared__ float sm[];
    float* Wsh   = sm;                         // 92 rows * 512 floats (46 per half)
    float* in2   = sm + 92 * 512;              // 2 h buffers x 512 float4 = 16KB
    u64*  exch_u = (u64*)(in2 + 4096);         // 8 x 256 u64 = 16KB
    const int tid = threadIdx.x;
    const int n  = tid & 127;
    const int kg = tid >> 7;                   // k-half
    const int R0 = blockIdx.x * 8;

    // load 92 weight rows: rows 0..45 = k 0..45 (low), rows 46..91 = k 64..109 (high)
    for (int i = tid; i < 92 * 128; i += 256) {
        int r = i >> 7, c = i & 127;
        int srcr = (r < 46) ? r : (r + 18);
        ((float4*)Wsh)[i] = ((const float4*)Wr)[srcr * 128 + c];
    }
    // register rows: k = kg*64 + 46 + j, j=0..17
    ulonglong2 wreg[KRH];
    #pragma unroll
    for (int j = 0; j < KRH; j++)
        wreg[j] = ((const ulonglong2*)Wr)[(kg * 64 + 46 + j) * 128 + n];

    for (int i = tid; i < 1024; i += 256)
        ((float4*)in2)[i] = make_float4(0.f, 0.f, 0.f, 0.f);
    __syncthreads();

    const ulonglong2* Wsh_u2 = (const ulonglong2*)Wsh;

    float cst[4] = {0.f, 0.f, 0.f, 0.f};
    // this thread activates rows R0 + kg*4 .. +3
    const float4* xp = (const float4*)xw + ((size_t)(R0 + kg * 4) * TSTEPS) * 128 + n;
    const size_t RS = (size_t)TSTEPS * 128;

    const int own_base = kg * 4;
    const int oth_base = 4 - kg * 4;   // rows stored for the partner
    const int partner = tid ^ 128;

    for (int t = 0; t < TSTEPS; t++) {
        // gate seeds for my 4 rows (latency hidden by k-loop)
        float4 xg[4];
        #pragma unroll
        for (int r = 0; r < 4; r++)
            xg[r] = xp[(size_t)r * RS + (size_t)t * 128];

        const ulonglong2* rb = (const ulonglong2*)in2 + ((t + 1) & 1) * 512;
        float4* wb = (float4*)in2 + (t & 1) * 512;

        u64 aif[8], ago[8];
        #pragma unroll
        for (int r = 0; r < 8; r++) { aif[r] = 0; ago[r] = 0; }

        // smem-resident weight rows of my half: row = kg*46 + j, k_act = kg*64 + j
        #pragma unroll 2
        for (int j = 0; j < KSH; j++) {
            ulonglong2 w = Wsh_u2[(kg * 46 + j) * 128 + n];
            const ulonglong2* hp = rb + (kg * 64 + j) * 4;
            ulonglong2 h01 = hp[0], h23 = hp[1], h45 = hp[2], h67 = hp[3];
            fma2(aif[0], w.x, h01.x); fma2(ago[0], w.y, h01.x);
            fma2(aif[1], w.x, h01.y); fma2(ago[1], w.y, h01.y);
            fma2(aif[2], w.x, h23.x); fma2(ago[2], w.y, h23.x);
            fma2(aif[3], w.x, h23.y); fma2(ago[3], w.y, h23.y);
            fma2(aif[4], w.x, h45.x); fma2(ago[4], w.y, h45.x);
            fma2(aif[5], w.x, h45.y); fma2(ago[5], w.y, h45.y);
            fma2(aif[6], w.x, h67.x); fma2(ago[6], w.y, h67.x);
            fma2(aif[7], w.x, h67.y); fma2(ago[7], w.y, h67.y);
        }
        // register-resident rows: k_act = kg*64 + 46 + j
        #pragma unroll
        for (int j = 0; j < KRH; j++) {
            const ulonglong2* hp = rb + (kg * 64 + 46 + j) * 4;
            ulonglong2 h01 = hp[0], h23 = hp[1], h45 = hp[2], h67 = hp[3];
            fma2(aif[0], wreg[j].x, h01.x); fma2(ago[0], wreg[j].y, h01.x);
            fma2(aif[1], wreg[j].x, h01.y); fma2(ago[1], wreg[j].y, h01.y);
            fma2(aif[2], wreg[j].x, h23.x); fma2(ago[2], wreg[j].y, h23.x);
            fma2(aif[3], wreg[j].x, h23.y); fma2(ago[3], wreg[j].y, h23.y);
            fma2(aif[4], wreg[j].x, h45.x); fma2(ago[4], wreg[j].y, h45.x);
            fma2(aif[5], wreg[j].x, h45.y); fma2(ago[5], wreg[j].y, h45.y);
            fma2(aif[6], wreg[j].x, h67.x); fma2(ago[6], wreg[j].y, h67.x);
            fma2(aif[7], wreg[j].x, h67.y); fma2(ago[7], wreg[j].y, h67.y);
        }

        // export partial gates for the rows the partner activates
        #pragma unroll
        for (int i = 0; i < 4; i++) {
            exch_u[i * 256 + tid]       = aif[oth_base + i];
            exch_u[(4 + i) * 256 + tid] = ago[oth_base + i];
        }
        __syncthreads();

        // merge partner's partials into my rows
        #pragma unroll
        for (int i = 0; i < 4; i++) {
            add2(aif[own_base + i], exch_u[i * 256 + partner]);
            add2(ago[own_base + i], exch_u[(4 + i) * 256 + partner]);
        }

        float hv[4];
        #pragma unroll
        for (int r = 0; r < 4; r++) {
            float gi, gf, gg, go;
            unpk(aif[own_base + r], gi, gf); unpk(ago[own_base + r], gg, go);
            gi += xg[r].x; gf += xg[r].y; gg += xg[r].z; go += xg[r].w;
            float iv = sigf(gi), fv = sigf(gf), gv = tanhf_(gg), ov = sigf(go);
            float cc = fv * cst[r] + iv * gv;
            cst[r] = cc;
            hv[r] = ov * tanhf_(cc);
        }

        // publish my 4 rows duplicated: wb[n*4 + kg*2 + j] = (h2j,h2j,h2j+1,h2j+1)
        wb[n * 4 + kg * 2 + 0] = make_float4(hv[0], hv[0], hv[1], hv[1]);
        wb[n * 4 + kg * 2 + 1] = make_float4(hv[2], hv[2], hv[3], hv[3]);

        if (LAYER == 0) {
            float* o = hout + ((size_t)t * BATCH + R0 + kg * 4) * HID + n;
            #pragma unroll
            for (int r = 0; r < 4; r++) o[r * HID] = hv[r];
        } else {
            if (t == TSTEPS - 1) {
                float* o = hout + (size_t)(R0 + kg * 4) * HID + n;
                #pragma unroll
                for (int r = 0; r < 4; r++) o[r * HID] = hv[r];
            }
        }
        __syncthreads();   // h(t) + exch consumption complete before next step
    }
}

// ---------------- batchnorm statistics ----------------
__global__ void bn_stats_kernel() {
    int n = blockIdx.x;
    int tid = threadIdx.x;
    float s = 0.f, ss = 0.f;
    for (int b = tid; b < BATCH; b += 256) {
        float v = g_last[(size_t)b * HID + n];
        s += v; ss += v * v;
    }
    __shared__ float sh1[256], sh2[256];
    sh1[tid] = s; sh2[tid] = ss;
    __syncthreads();
    for (int o = 128; o > 0; o >>= 1) {
        if (tid < o) { sh1[tid] += sh1[tid + o]; sh2[tid] += sh2[tid + o]; }
        __syncthreads();
    }
    if (tid == 0) {
        float mu = sh1[0] * (1.0f / BATCH);
        float var = sh2[0] * (1.0f / BATCH) - mu * mu;
        g_mu[n] = mu;
        g_rstd[n] = rsqrtf(var + 1e-5f);
    }
}

// ---------------- MLP head ----------------
__global__ void head_kernel(const float* __restrict__ gamma, const float* __restrict__ beta,
                            const float* __restrict__ W1, const float* __restrict__ b1,
                            const float* __restrict__ W2, const float* __restrict__ b2,
                            float* __restrict__ out) {
    __shared__ float w1sh[128 * 33];
    __shared__ float scale_sh[128], shift_sh[128];
    int tid = threadIdx.x;
    for (int i = tid; i < 32 * 128; i += 256) {
        int j = i >> 7, n = i & 127;
        w1sh[n * 33 + j] = W1[i];
    }
    for (int i = tid; i < 128; i += 256) {
        float rs = g_rstd[i] * gamma[i];
        scale_sh[i] = rs;
        shift_sh[i] = beta[i] - g_mu[i] * rs;
    }
    __syncthreads();
    int w = tid >> 5, lane = tid & 31;
    int b = blockIdx.x * 8 + w;
    const float* lrow = g_last + (size_t)b * HID;
    float z = b1[lane];
    #pragma unroll 4
    for (int n = 0; n < 128; n++) {
        float nv = fmaf(lrow[n], scale_sh[n], shift_sh[n]);
        z = fmaf(w1sh[n * 33 + lane], nv, z);
    }
    z = fmaxf(z, 0.0f);
    float acc = z * W2[lane];
    #pragma unroll
    for (int o = 16; o > 0; o >>= 1) acc += __shfl_down_sync(0xffffffffu, acc, o);
    if (lane == 0) out[b] = acc + b2[0];
}

// ---------------- launcher ----------------
extern "C" void kernel_launch(void* const* d_in, const int* in_sizes, int n_in,
                              void* d_out, int out_size) {
    (void)in_sizes; (void)n_in; (void)out_size;
    const float* x    = (const float*)d_in[0];
    const float* Wih0 = (const float*)d_in[1];
    const float* Whh0 = (const float*)d_in[2];
    const float* bih0 = (const float*)d_in[3];
    const float* bhh0 = (const float*)d_in[4];
    const float* Wih1 = (const float*)d_in[5];
    const float* Whh1 = (const float*)d_in[6];
    const float* bih1 = (const float*)d_in[7];
    const float* bhh1 = (const float*)d_in[8];
    const float* gamma = (const float*)d_in[9];
    const float* beta  = (const float*)d_in[10];
    const float* W1 = (const float*)d_in[11];
    const float* b1 = (const float*)d_in[12];
    const float* W2 = (const float*)d_in[13];
    const float* b2 = (const float*)d_in[14];
    float* out = (float*)d_out;

    float *p_Wr0, *p_Wr1, *p_Wi0r, *p_Wi1r, *p_b0r, *p_b1r, *p_xw, *p_h1, *p_last;
    cudaGetSymbolAddress((void**)&p_Wr0, g_Wr0);
    cudaGetSymbolAddress((void**)&p_Wr1, g_Wr1);
    cudaGetSymbolAddress((void**)&p_Wi0r, g_Wi0r);
    cudaGetSymbolAddress((void**)&p_Wi1r, g_Wi1r);
    cudaGetSymbolAddress((void**)&p_b0r, g_b0r);
    cudaGetSymbolAddress((void**)&p_b1r, g_b1r);
    cudaGetSymbolAddress((void**)&p_xw,  g_xw);
    cudaGetSymbolAddress((void**)&p_h1,  g_h1);
    cudaGetSymbolAddress((void**)&p_last, g_last);

    constexpr int SMR  = (92 * 512 + 4096 + 4096) * 4;     // 221,184 B
    constexpr int SMG1 = (128 * 256 + 128 * 128) * 4;      // 196,608 B
    static bool attr_done = false;
    if (!attr_done) {
        cudaFuncSetAttribute(rec_kernel<0>, cudaFuncAttributeMaxDynamicSharedMemorySize, SMR);
        cudaFuncSetAttribute(rec_kernel<1>, cudaFuncAttributeMaxDynamicSharedMemorySize, SMR);
        cudaFuncSetAttribute(gemm_h_kernel, cudaFuncAttributeMaxDynamicSharedMemorySize, SMG1);
        attr_done = true;
    }

    prep_kernel<<<256, 256>>>(Wih0, Whh0, bih0, bhh0, Wih1, Whh1, bih1, bhh1);
    gemm_x_kernel<<<512, 256>>>(x, p_Wi0r, p_b0r, p_xw);                         // xw0
    rec_kernel<0><<<BATCH / 8, 256, SMR>>>(p_xw, p_Wr0, p_h1);                   // layer 0
    gemm_h_kernel<<<dim3(GRIDX_H, 2), 256, SMG1>>>(p_h1, p_Wi1r, p_b1r, p_xw);   // xw1
    rec_kernel<1><<<BATCH / 8, 256, SMR>>>(p_xw, p_Wr1, p_last);                 // layer 1
    bn_stats_kernel<<<HID, 256>>>();
    head_kernel<<<BATCH / 8, 256>>>(gamma, beta, W1, b1, W2, b2, out);
}

// round 14
// speedup vs baseline: 1.7950x; 1.7950x over previous
#include <cuda_runtime.h>
#include <cstdint>
#include <cstddef>

#define BATCH 1024
#define TSTEPS 512
#define DIN 14
#define HID 128
#define KS 104                 // Whh rows resident in SMEM
#define KR 24                  // Whh rows resident in registers
#define NT_H 16384             // gemm_h tiles: (B*T)/32
#define GRIDX_H 74             // gemm_h grid.x (148 CTAs total with 2 cls)

typedef unsigned long long u64;

// ---------------- device scratch ----------------
__device__ float g_Wr0[128 * 512];     // Whh0 reordered [k][n*4+g]
__device__ float g_Wr1[128 * 512];     // Whh1 reordered
__device__ float g_Wi0r[14 * 512];     // Wih0 reordered [k][n*4+g]
__device__ float g_Wi1r[128 * 512];    // Wih1 reordered
__device__ float g_b0r[512];           // (bih0+bhh0) reordered [n*4+g]
__device__ float g_b1r[512];
__device__ float g_xw[(size_t)BATCH * TSTEPS * 512];   // 1 GB; [b*T+t][512]
__device__ float g_h1[(size_t)TSTEPS * BATCH * HID];   // 256 MB; [t*B+b][128]
__device__ float g_last[BATCH * HID];
__device__ float g_mu[HID];
__device__ float g_rstd[HID];

// ---------------- helpers ----------------
__device__ __forceinline__ u64 pack2(float lo, float hi) {
    u64 r;
    asm("mov.b64 %0, {%1, %2};" : "=l"(r)
        : "r"(__float_as_uint(lo)), "r"(__float_as_uint(hi)));
    return r;
}
__device__ __forceinline__ void fma2(u64& d, u64 a, u64 b) {
    asm("fma.rn.f32x2 %0, %1, %2, %0;" : "+l"(d) : "l"(a), "l"(b));
}
__device__ __forceinline__ void unpk(u64 v, float& lo, float& hi) {
    unsigned int l, h;
    asm("mov.b64 {%0, %1}, %2;" : "=r"(l), "=r"(h) : "l"(v));
    lo = __uint_as_float(l); hi = __uint_as_float(h);
}
__device__ __forceinline__ float sigf(float x) {
    return __fdividef(1.0f, 1.0f + __expf(-x));
}
__device__ __forceinline__ float tanhf_(float x) {
    return __fdividef(2.0f, 1.0f + __expf(-2.0f * x)) - 1.0f;
}

// ---------------- prep: reorder weights [k][n*4+g], fuse biases ----------------
__global__ void prep_kernel(const float* __restrict__ Wih0, const float* __restrict__ Whh0,
                            const float* __restrict__ bih0, const float* __restrict__ bhh0,
                            const float* __restrict__ Wih1, const float* __restrict__ Whh1,
                            const float* __restrict__ bih1, const float* __restrict__ bhh1) {
    int idx0 = blockIdx.x * blockDim.x + threadIdx.x;
    int stride = gridDim.x * blockDim.x;
    for (int i = idx0; i < 128 * 512; i += stride) {
        int k = i >> 9, j = i & 511, n = j >> 2, g = j & 3;
        g_Wr0[i]  = Whh0[(g * 128 + n) * 128 + k];
        g_Wr1[i]  = Whh1[(g * 128 + n) * 128 + k];
        g_Wi1r[i] = Wih1[(g * 128 + n) * 128 + k];
    }
    for (int i = idx0; i < 14 * 512; i += stride) {
        int k = i / 512, j = i % 512, n = j >> 2, g = j & 3;
        g_Wi0r[i] = Wih0[(g * 128 + n) * 14 + k];
    }
    for (int i = idx0; i < 512; i += stride) {
        int n = i >> 2, g = i & 3;
        g_b0r[i] = bih0[g * 128 + n] + bhh0[g * 128 + n];
        g_b1r[i] = bih1[g * 128 + n] + bhh1[g * 128 + n];
    }
}

// ---------------- gemm0: xw0[m][512] = x[m][14] @ Wi0r + b0, m = b*T+t ----------------
__global__ void __launch_bounds__(256, 1) gemm_x_kernel(
    const float* __restrict__ X, const float* __restrict__ Wr,
    const float* __restrict__ bias, float* __restrict__ XW)
{
    __shared__ float Wsh[14 * 512];
    __shared__ float xs[14 * 16];   // duplicated inputs: per k, 8 rows as (x,x) pairs
    const int tid = threadIdx.x;
    const int n = tid & 127;
    const int half = tid >> 7;

    for (int i = tid; i < 14 * 128; i += 256)
        ((float4*)Wsh)[i] = ((const float4*)Wr)[i];
    float4 bv = ((const float4*)bias)[n];
    const u64 bif = pack2(bv.x, bv.y), bgo = pack2(bv.z, bv.w);

    const bool stager = tid < 112;
    const int sr = tid / 14, sk = tid - sr * 14;
    const size_t m0b = (size_t)blockIdx.x * 1024;
    float pv = stager ? X[(m0b + sr) * 14 + sk] : 0.0f;
    __syncthreads();

    const ulonglong2* Wsh_u2 = (const ulonglong2*)Wsh;
    const ulonglong2* xs_u2  = (const ulonglong2*)xs;
    u64* xs_u = (u64*)xs;
    float4* XW4 = (float4*)XW;

    for (int tile = 0; tile < 128; tile++) {
        if (stager) xs_u[sk * 8 + sr] = pack2(pv, pv);
        __syncthreads();
        if (tile < 127 && stager)
            pv = X[(m0b + (size_t)(tile + 1) * 8 + sr) * 14 + sk];

        u64 aif0 = bif, aif1 = bif, aif2 = bif, aif3 = bif;
        u64 ago0 = bgo, ago1 = bgo, ago2 = bgo, ago3 = bgo;
        #pragma unroll
        for (int k = 0; k < 14; k++) {
            ulonglong2 w   = Wsh_u2[k * 128 + n];
            ulonglong2 h01 = xs_u2[k * 4 + half * 2];
            ulonglong2 h23 = xs_u2[k * 4 + half * 2 + 1];
            fma2(aif0, w.x, h01.x); fma2(ago0, w.y, h01.x);
            fma2(aif1, w.x, h01.y); fma2(ago1, w.y, h01.y);
            fma2(aif2, w.x, h23.x); fma2(ago2, w.y, h23.x);
            fma2(aif3, w.x, h23.y); fma2(ago3, w.y, h23.y);
        }
        size_t m0 = m0b + (size_t)tile * 8 + half * 4;
        float a, b, c, d;
        unpk(aif0, a, b); unpk(ago0, c, d); XW4[(m0 + 0) * 128 + n] = make_float4(a, b, c, d);
        unpk(aif1, a, b); unpk(ago1, c, d); XW4[(m0 + 1) * 128 + n] = make_float4(a, b, c, d);
        unpk(aif2, a, b); unpk(ago2, c, d); XW4[(m0 + 2) * 128 + n] = make_float4(a, b, c, d);
        unpk(aif3, a, b); unpk(ago3, c, d); XW4[(m0 + 3) * 128 + n] = make_float4(a, b, c, d);
        __syncthreads();
    }
}

// ---------------- gemm1: xw1[(b*T+t)][512] = h1[(t*B+b)][128] @ Wi1r + b1 ----------------
// 32-row M-tiles, each thread 8 rows x 1 n-unit. Inputs read via broadcast LDS.
// grid (GRIDX_H, 2); cls = blockIdx.y picks n-half.
// Staging lane map is conflict-free: sr = tid&31 (contiguous lanes per store).
__global__ void __launch_bounds__(256, 1) gemm_h_kernel(
    const float* __restrict__ X, const float* __restrict__ Wr,
    const float* __restrict__ bias, float* __restrict__ XW)
{
    extern __shared__ float sm[];
    float* Wsh = sm;                 // 128 k * 256 floats (cls half)
    u64*   xs_u = (u64*)(sm + 128 * 256);  // 128 k * 32 dup u64
    const int tid = threadIdx.x;
    const int cls = blockIdx.y;
    const int nl = tid & 63;         // n-unit within half
    const int rg = tid >> 6;         // row-group 0..3 (8 rows each)
    const int ng = cls * 64 + nl;    // global n-unit

    for (int i = tid; i < 128 * 64; i += 256) {
        int k = i >> 6, j4 = i & 63;
        ((float4*)Wsh)[i] = ((const float4*)Wr)[k * 128 + cls * 64 + j4];
    }
    float4 bv = ((const float4*)bias)[ng];
    const u64 bif = pack2(bv.x, bv.y), bgo = pack2(bv.z, bv.w);

    // staging map (conflict-free stores): sr = row-in-tile = lane, cq = warp picks 16 k
    const int sr = tid & 31, cq = tid >> 5;
    const float4* X4 = (const float4*)X;
    const ulonglong2* Wsh_u2 = (const ulonglong2*)Wsh;
    const ulonglong2* xs_u2  = (const ulonglong2*)xs_u;
    float4* XW4 = (float4*)XW;

    int tile = blockIdx.x;
    float4 px0, px1, px2, px3;
    {
        size_t mr = (size_t)tile * 32 + sr;
        px0 = X4[mr * 32 + cq * 4 + 0];
        px1 = X4[mr * 32 + cq * 4 + 1];
        px2 = X4[mr * 32 + cq * 4 + 2];
        px3 = X4[mr * 32 + cq * 4 + 3];
    }

    for (; tile < NT_H; tile += GRIDX_H) {
        // stage duplicated inputs: xs[k][sr] = (x,x); k = cq*16 + 4q + j
        {
            int k0 = cq * 16;
            xs_u[(k0 + 0)  * 32 + sr] = pack2(px0.x, px0.x);
            xs_u[(k0 + 1)  * 32 + sr] = pack2(px0.y, px0.y);
            xs_u[(k0 + 2)  * 32 + sr] = pack2(px0.z, px0.z);
            xs_u[(k0 + 3)  * 32 + sr] = pack2(px0.w, px0.w);
            xs_u[(k0 + 4)  * 32 + sr] = pack2(px1.x, px1.x);
            xs_u[(k0 + 5)  * 32 + sr] = pack2(px1.y, px1.y);
            xs_u[(k0 + 6)  * 32 + sr] = pack2(px1.z, px1.z);
            xs_u[(k0 + 7)  * 32 + sr] = pack2(px1.w, px1.w);
            xs_u[(k0 + 8)  * 32 + sr] = pack2(px2.x, px2.x);
            xs_u[(k0 + 9)  * 32 + sr] = pack2(px2.y, px2.y);
            xs_u[(k0 + 10) * 32 + sr] = pack2(px2.z, px2.z);
            xs_u[(k0 + 11) * 32 + sr] = pack2(px2.w, px2.w);
            xs_u[(k0 + 12) * 32 + sr] = pack2(px3.x, px3.x);
            xs_u[(k0 + 13) * 32 + sr] = pack2(px3.y, px3.y);
            xs_u[(k0 + 14) * 32 + sr] = pack2(px3.z, px3.z);
            xs_u[(k0 + 15) * 32 + sr] = pack2(px3.w, px3.w);
        }
        __syncthreads();

        int tn = tile + GRIDX_H;
        if (tn < NT_H) {
            size_t mr = (size_t)tn * 32 + sr;
            px0 = X4[mr * 32 + cq * 4 + 0];
            px1 = X4[mr * 32 + cq * 4 + 1];
            px2 = X4[mr * 32 + cq * 4 + 2];
            px3 = X4[mr * 32 + cq * 4 + 3];
        }

        u64 aif[8], ago[8];
        #pragma unroll
        for (int j = 0; j < 8; j++) { aif[j] = bif; ago[j] = bgo; }

        #pragma unroll 8
        for (int k = 0; k < 128; k++) {
            ulonglong2 w  = Wsh_u2[k * 64 + nl];
            ulonglong2 p0 = xs_u2[k * 16 + rg * 4];
            ulonglong2 p1 = xs_u2[k * 16 + rg * 4 + 1];
            ulonglong2 p2 = xs_u2[k * 16 + rg * 4 + 2];
            ulonglong2 p3 = xs_u2[k * 16 + rg * 4 + 3];
            fma2(aif[0], w.x, p0.x); fma2(ago[0], w.y, p0.x);
            fma2(aif[1], w.x, p0.y); fma2(ago[1], w.y, p0.y);
            fma2(aif[2], w.x, p1.x); fma2(ago[2], w.y, p1.x);
            fma2(aif[3], w.x, p1.y); fma2(ago[3], w.y, p1.y);
            fma2(aif[4], w.x, p2.x); fma2(ago[4], w.y, p2.x);
            fma2(aif[5], w.x, p2.y); fma2(ago[5], w.y, p2.y);
            fma2(aif[6], w.x, p3.x); fma2(ago[6], w.y, p3.x);
            fma2(aif[7], w.x, p3.y); fma2(ago[7], w.y, p3.y);
        }

        #pragma unroll
        for (int jj = 0; jj < 8; jj++) {
            int mh = tile * 32 + rg * 8 + jj;   // h1-order index = t*B + b
            int b_ = mh & 1023;
            int t_ = mh >> 10;
            float a, b, c, d;
            unpk(aif[jj], a, b); unpk(ago[jj], c, d);
            XW4[((size_t)b_ * TSTEPS + t_) * 128 + ng] = make_float4(a, b, c, d);
        }
        __syncthreads();
    }
}

// ---------------- recurrence v3: 128 threads, 8 rows per THREAD ----------------
// Per SM per k = 32 wavefronts = 32 fma cycles (balanced).
// LAYER 0: hout = g_h1 [t*B+b][128]   LAYER 1: hout = g_last [b][128]
template <int LAYER>
__global__ void __launch_bounds__(128, 1) rec_kernel(
    const float* __restrict__ xw,   // [b*T+t][512], gates precomputed incl. bias
    const float* __restrict__ Wr,   // [128][512] reordered
    float* __restrict__ hout)
{
    extern __shared__ float sm[];
    float* Wsh = sm;                 // KS*512 floats
    float* in2 = sm + KS * 512;      // 2 buffers x 128 k x 8 rows x (h,h) = 4096 floats
    const int tid = threadIdx.x;     // n-unit index, 0..127
    const int R0 = blockIdx.x * 8;

    for (int i = tid; i < KS * 128; i += 128)
        ((float4*)Wsh)[i] = ((const float4*)Wr)[i];

    ulonglong2 wreg[KR];
    #pragma unroll
    for (int j = 0; j < KR; j++)
        wreg[j] = ((const ulonglong2*)Wr)[(KS + j) * 128 + tid];

    for (int i = tid; i < 1024; i += 128)
        ((float4*)in2)[i] = make_float4(0.f, 0.f, 0.f, 0.f);
    __syncthreads();

    const ulonglong2* Wsh_u2 = (const ulonglong2*)Wsh;

    float cst[8];
    #pragma unroll
    for (int r = 0; r < 8; r++) cst[r] = 0.0f;

    const float4* xp = (const float4*)xw + ((size_t)R0 * TSTEPS) * 128 + tid;
    const size_t RS = (size_t)TSTEPS * 128;   // float4 stride per batch row

    for (int t = 0; t < TSTEPS; t++) {
        // prefetch this step's gate seeds for all 8 rows (hidden by k-loop)
        float4 xg[8];
        #pragma unroll
        for (int r = 0; r < 8; r++)
            xg[r] = xp[(size_t)r * RS + (size_t)t * 128];

        const ulonglong2* rb = (const ulonglong2*)in2 + ((t + 1) & 1) * 512;
        float4* wb = (float4*)in2 + (t & 1) * 512;

        u64 aif[8], ago[8];
        #pragma unroll
        for (int r = 0; r < 8; r++) { aif[r] = 0; ago[r] = 0; }

        #pragma unroll 8
        for (int k = 0; k < KS; k++) {
            ulonglong2 w   = Wsh_u2[k * 128 + tid];
            ulonglong2 h01 = rb[k * 4 + 0];
            ulonglong2 h23 = rb[k * 4 + 1];
            ulonglong2 h45 = rb[k * 4 + 2];
            ulonglong2 h67 = rb[k * 4 + 3];
            fma2(aif[0], w.x, h01.x); fma2(ago[0], w.y, h01.x);
            fma2(aif[1], w.x, h01.y); fma2(ago[1], w.y, h01.y);
            fma2(aif[2], w.x, h23.x); fma2(ago[2], w.y, h23.x);
            fma2(aif[3], w.x, h23.y); fma2(ago[3], w.y, h23.y);
            fma2(aif[4], w.x, h45.x); fma2(ago[4], w.y, h45.x);
            fma2(aif[5], w.x, h45.y); fma2(ago[5], w.y, h45.y);
            fma2(aif[6], w.x, h67.x); fma2(ago[6], w.y, h67.x);
            fma2(aif[7], w.x, h67.y); fma2(ago[7], w.y, h67.y);
        }
        #pragma unroll
        for (int j = 0; j < KR; j++) {
            int k = KS + j;
            ulonglong2 h01 = rb[k * 4 + 0];
            ulonglong2 h23 = rb[k * 4 + 1];
            ulonglong2 h45 = rb[k * 4 + 2];
            ulonglong2 h67 = rb[k * 4 + 3];
            fma2(aif[0], wreg[j].x, h01.x); fma2(ago[0], wreg[j].y, h01.x);
            fma2(aif[1], wreg[j].x, h01.y); fma2(ago[1], wreg[j].y, h01.y);
            fma2(aif[2], wreg[j].x, h23.x); fma2(ago[2], wreg[j].y, h23.x);
            fma2(aif[3], wreg[j].x, h23.y); fma2(ago[3], wreg[j].y, h23.y);
            fma2(aif[4], wreg[j].x, h45.x); fma2(ago[4], wreg[j].y, h45.x);
            fma2(aif[5], wreg[j].x, h45.y); fma2(ago[5], wreg[j].y, h45.y);
            fma2(aif[6], wreg[j].x, h67.x); fma2(ago[6], wreg[j].y, h67.x);
            fma2(aif[7], wreg[j].x, h67.y); fma2(ago[7], wreg[j].y, h67.y);
        }

        float hv[8];
        #pragma unroll
        for (int r = 0; r < 8; r++) {
            float gi, gf, gg, go;
            unpk(aif[r], gi, gf); unpk(ago[r], gg, go);
            gi += xg[r].x; gf += xg[r].y; gg += xg[r].z; go += xg[r].w;
            float iv = sigf(gi), fv = sigf(gf), gv = tanhf_(gg), ov = sigf(go);
            float cc = fv * cst[r] + iv * gv;
            cst[r] = cc;
            hv[r] = ov * tanhf_(cc);
        }

        // publish h(t) duplicated: wb[n*4 + j] = (h2j, h2j, h2j+1, h2j+1)
        wb[tid * 4 + 0] = make_float4(hv[0], hv[0], hv[1], hv[1]);
        wb[tid * 4 + 1] = make_float4(hv[2], hv[2], hv[3], hv[3]);
        wb[tid * 4 + 2] = make_float4(hv[4], hv[4], hv[5], hv[5]);
        wb[tid * 4 + 3] = make_float4(hv[6], hv[6], hv[7], hv[7]);

        if (LAYER == 0) {
            float* o = hout + ((size_t)t * BATCH + R0) * HID + tid;
            #pragma unroll
            for (int r = 0; r < 8; r++) o[r * HID] = hv[r];
        } else {
            if (t == TSTEPS - 1) {
                float* o = hout + (size_t)R0 * HID + tid;
                #pragma unroll
                for (int r = 0; r < 8; r++) o[r * HID] = hv[r];
            }
        }
        __syncthreads();   // h(t) visible before next step's k-loop
    }
}

// ---------------- batchnorm statistics ----------------
__global__ void bn_stats_kernel() {
    int n = blockIdx.x;
    int tid = threadIdx.x;
    float s = 0.f, ss = 0.f;
    for (int b = tid; b < BATCH; b += 256) {
        float v = g_last[(size_t)b * HID + n];
        s += v; ss += v * v;
    }
    __shared__ float sh1[256], sh2[256];
    sh1[tid] = s; sh2[tid] = ss;
    __syncthreads();
    for (int o = 128; o > 0; o >>= 1) {
        if (tid < o) { sh1[tid] += sh1[tid + o]; sh2[tid] += sh2[tid + o]; }
        __syncthreads();
    }
    if (tid == 0) {
        float mu = sh1[0] * (1.0f / BATCH);
        float var = sh2[0] * (1.0f / BATCH) - mu * mu;
        g_mu[n] = mu;
        g_rstd[n] = rsqrtf(var + 1e-5f);
    }
}

// ---------------- MLP head ----------------
__global__ void head_kernel(const float* __restrict__ gamma, const float* __restrict__ beta,
                            const float* __restrict__ W1, const float* __restrict__ b1,
                            const float* __restrict__ W2, const float* __restrict__ b2,
                            float* __restrict__ out) {
    __shared__ float w1sh[128 * 33];
    __shared__ float scale_sh[128], shift_sh[128];
    int tid = threadIdx.x;
    for (int i = tid; i < 32 * 128; i += 256) {
        int j = i >> 7, n = i & 127;
        w1sh[n * 33 + j] = W1[i];
    }
    for (int i = tid; i < 128; i += 256) {
        float rs = g_rstd[i] * gamma[i];
        scale_sh[i] = rs;
        shift_sh[i] = beta[i] - g_mu[i] * rs;
    }
    __syncthreads();
    int w = tid >> 5, lane = tid & 31;
    int b = blockIdx.x * 8 + w;
    const float* lrow = g_last + (size_t)b * HID;
    float z = b1[lane];
    #pragma unroll 4
    for (int n = 0; n < 128; n++) {
        float nv = fmaf(lrow[n], scale_sh[n], shift_sh[n]);
        z = fmaf(w1sh[n * 33 + lane], nv, z);
    }
    z = fmaxf(z, 0.0f);
    float acc = z * W2[lane];
    #pragma unroll
    for (int o = 16; o > 0; o >>= 1) acc += __shfl_down_sync(0xffffffffu, acc, o);
    if (lane == 0) out[b] = acc + b2[0];
}

// ---------------- launcher ----------------
extern "C" void kernel_launch(void* const* d_in, const int* in_sizes, int n_in,
                              void* d_out, int out_size) {
    (void)in_sizes; (void)n_in; (void)out_size;
    const float* x    = (const float*)d_in[0];
    const float* Wih0 = (const float*)d_in[1];
    const float* Whh0 = (const float*)d_in[2];
    const float* bih0 = (const float*)d_in[3];
    const float* bhh0 = (const float*)d_in[4];
    const float* Wih1 = (const float*)d_in[5];
    const float* Whh1 = (const float*)d_in[6];
    const float* bih1 = (const float*)d_in[7];
    const float* bhh1 = (const float*)d_in[8];
    const float* gamma = (const float*)d_in[9];
    const float* beta  = (const float*)d_in[10];
    const float* W1 = (const float*)d_in[11];
    const float* b1 = (const float*)d_in[12];
    const float* W2 = (const float*)d_in[13];
    const float* b2 = (const float*)d_in[14];
    float* out = (float*)d_out;

    float *p_Wr0, *p_Wr1, *p_Wi0r, *p_Wi1r, *p_b0r, *p_b1r, *p_xw, *p_h1, *p_last;
    cudaGetSymbolAddress((void**)&p_Wr0, g_Wr0);
    cudaGetSymbolAddress((void**)&p_Wr1, g_Wr1);
    cudaGetSymbolAddress((void**)&p_Wi0r, g_Wi0r);
    cudaGetSymbolAddress((void**)&p_Wi1r, g_Wi1r);
    cudaGetSymbolAddress((void**)&p_b0r, g_b0r);
    cudaGetSymbolAddress((void**)&p_b1r, g_b1r);
    cudaGetSymbolAddress((void**)&p_xw,  g_xw);
    cudaGetSymbolAddress((void**)&p_h1,  g_h1);
    cudaGetSymbolAddress((void**)&p_last, g_last);

    constexpr int SMR  = (KS * 512 + 4096) * 4;            // 229,376 B
    constexpr int SMG1 = (128 * 256 + 128 * 64) * 4;       // 163,840 B
    static bool attr_done = false;
    if (!attr_done) {
        cudaFuncSetAttribute(rec_kernel<0>, cudaFuncAttributeMaxDynamicSharedMemorySize, SMR);
        cudaFuncSetAttribute(rec_kernel<1>, cudaFuncAttributeMaxDynamicSharedMemorySize, SMR);
        cudaFuncSetAttribute(gemm_h_kernel, cudaFuncAttributeMaxDynamicSharedMemorySize, SMG1);
        attr_done = true;
    }

    prep_kernel<<<256, 256>>>(Wih0, Whh0, bih0, bhh0, Wih1, Whh1, bih1, bhh1);
    gemm_x_kernel<<<512, 256>>>(x, p_Wi0r, p_b0r, p_xw);                         // xw0
    rec_kernel<0><<<BATCH / 8, 128, SMR>>>(p_xw, p_Wr0, p_h1);                   // layer 0
    gemm_h_kernel<<<dim3(GRIDX_H, 2), 256, SMG1>>>(p_h1, p_Wi1r, p_b1r, p_xw);   // xw1
    rec_kernel<1><<<BATCH / 8, 128, SMR>>>(p_xw, p_Wr1, p_last);                 // layer 1
    bn_stats_kernel<<<HID, 256>>>();
    head_kernel<<<BATCH / 8, 256>>>(gamma, beta, W1, b1, W2, b2, out);
}

// round 15
// speedup vs baseline: 2.2220x; 1.2379x over previous
#include <cuda_runtime.h>
#include <cstdint>
#include <cstddef>

#define BATCH 1024
#define TSTEPS 512
#define DIN 14
#define HID 128
#define KS 104                 // Whh rows resident in SMEM
#define KR 24                  // Whh rows resident in registers
#define NT_H 16384             // gemm_h tiles: (B*T)/32
#define GRIDX_H 74             // gemm_h grid.x (148 CTAs total with 2 cls)

typedef unsigned long long u64;

// ---------------- device scratch ----------------
__device__ float g_Wr0[128 * 512];     // Whh0 reordered [k][n*4+g]
__device__ float g_Wr1[128 * 512];     // Whh1 reordered
__device__ float g_Wi0r[14 * 512];     // Wih0 reordered [k][n*4+g]
__device__ float g_Wi1r[128 * 512];    // Wih1 reordered
__device__ float g_b0r[512];           // (bih0+bhh0) reordered [n*4+g]
__device__ float g_b1r[512];
__device__ float g_xw[(size_t)BATCH * TSTEPS * 512];   // 1 GB; [b*T+t][512]
__device__ float g_h1[(size_t)TSTEPS * BATCH * HID];   // 256 MB; [t*B+b][128]
__device__ float g_last[BATCH * HID];
__device__ float g_mu[HID];
__device__ float g_rstd[HID];

// ---------------- helpers ----------------
__device__ __forceinline__ u64 pack2(float lo, float hi) {
    u64 r;
    asm("mov.b64 %0, {%1, %2};" : "=l"(r)
        : "r"(__float_as_uint(lo)), "r"(__float_as_uint(hi)));
    return r;
}
__device__ __forceinline__ void fma2(u64& d, u64 a, u64 b) {
    asm("fma.rn.f32x2 %0, %1, %2, %0;" : "+l"(d) : "l"(a), "l"(b));
}
__device__ __forceinline__ void unpk(u64 v, float& lo, float& hi) {
    unsigned int l, h;
    asm("mov.b64 {%0, %1}, %2;" : "=r"(l), "=r"(h) : "l"(v));
    lo = __uint_as_float(l); hi = __uint_as_float(h);
}
__device__ __forceinline__ float sigf(float x) {
    return __fdividef(1.0f, 1.0f + __expf(-x));
}
__device__ __forceinline__ float tanhf_(float x) {
    return __fdividef(2.0f, 1.0f + __expf(-2.0f * x)) - 1.0f;
}

// ---------------- prep: reorder weights [k][n*4+g], fuse biases ----------------
__global__ void prep_kernel(const float* __restrict__ Wih0, const float* __restrict__ Whh0,
                            const float* __restrict__ bih0, const float* __restrict__ bhh0,
                            const float* __restrict__ Wih1, const float* __restrict__ Whh1,
                            const float* __restrict__ bih1, const float* __restrict__ bhh1) {
    int idx0 = blockIdx.x * blockDim.x + threadIdx.x;
    int stride = gridDim.x * blockDim.x;
    for (int i = idx0; i < 128 * 512; i += stride) {
        int k = i >> 9, j = i & 511, n = j >> 2, g = j & 3;
        g_Wr0[i]  = Whh0[(g * 128 + n) * 128 + k];
        g_Wr1[i]  = Whh1[(g * 128 + n) * 128 + k];
        g_Wi1r[i] = Wih1[(g * 128 + n) * 128 + k];
    }
    for (int i = idx0; i < 14 * 512; i += stride) {
        int k = i / 512, j = i % 512, n = j >> 2, g = j & 3;
        g_Wi0r[i] = Wih0[(g * 128 + n) * 14 + k];
    }
    for (int i = idx0; i < 512; i += stride) {
        int n = i >> 2, g = i & 3;
        g_b0r[i] = bih0[g * 128 + n] + bhh0[g * 128 + n];
        g_b1r[i] = bih1[g * 128 + n] + bhh1[g * 128 + n];
    }
}

// ---------------- gemm0: xw0[m][512] = x[m][14] @ Wi0r + b0, m = b*T+t ----------------
// (unchanged — small kernel)
__global__ void __launch_bounds__(256, 1) gemm_x_kernel(
    const float* __restrict__ X, const float* __restrict__ Wr,
    const float* __restrict__ bias, float* __restrict__ XW)
{
    __shared__ float Wsh[14 * 512];
    __shared__ float xs[14 * 16];   // duplicated inputs: per k, 8 rows as (x,x) pairs
    const int tid = threadIdx.x;
    const int n = tid & 127;
    const int half = tid >> 7;

    for (int i = tid; i < 14 * 128; i += 256)
        ((float4*)Wsh)[i] = ((const float4*)Wr)[i];
    float4 bv = ((const float4*)bias)[n];
    const u64 bif = pack2(bv.x, bv.y), bgo = pack2(bv.z, bv.w);

    const bool stager = tid < 112;
    const int sr = tid / 14, sk = tid - sr * 14;
    const size_t m0b = (size_t)blockIdx.x * 1024;
    float pv = stager ? X[(m0b + sr) * 14 + sk] : 0.0f;
    __syncthreads();

    const ulonglong2* Wsh_u2 = (const ulonglong2*)Wsh;
    const ulonglong2* xs_u2  = (const ulonglong2*)xs;
    u64* xs_u = (u64*)xs;
    float4* XW4 = (float4*)XW;

    for (int tile = 0; tile < 128; tile++) {
        if (stager) xs_u[sk * 8 + sr] = pack2(pv, pv);
        __syncthreads();
        if (tile < 127 && stager)
            pv = X[(m0b + (size_t)(tile + 1) * 8 + sr) * 14 + sk];

        u64 aif0 = bif, aif1 = bif, aif2 = bif, aif3 = bif;
        u64 ago0 = bgo, ago1 = bgo, ago2 = bgo, ago3 = bgo;
        #pragma unroll
        for (int k = 0; k < 14; k++) {
            ulonglong2 w   = Wsh_u2[k * 128 + n];
            ulonglong2 h01 = xs_u2[k * 4 + half * 2];
            ulonglong2 h23 = xs_u2[k * 4 + half * 2 + 1];
            fma2(aif0, w.x, h01.x); fma2(ago0, w.y, h01.x);
            fma2(aif1, w.x, h01.y); fma2(ago1, w.y, h01.y);
            fma2(aif2, w.x, h23.x); fma2(ago2, w.y, h23.x);
            fma2(aif3, w.x, h23.y); fma2(ago3, w.y, h23.y);
        }
        size_t m0 = m0b + (size_t)tile * 8 + half * 4;
        float a, b, c, d;
        unpk(aif0, a, b); unpk(ago0, c, d); XW4[(m0 + 0) * 128 + n] = make_float4(a, b, c, d);
        unpk(aif1, a, b); unpk(ago1, c, d); XW4[(m0 + 1) * 128 + n] = make_float4(a, b, c, d);
        unpk(aif2, a, b); unpk(ago2, c, d); XW4[(m0 + 2) * 128 + n] = make_float4(a, b, c, d);
        unpk(aif3, a, b); unpk(ago3, c, d); XW4[(m0 + 3) * 128 + n] = make_float4(a, b, c, d);
        __syncthreads();
    }
}

// ---------------- gemm1 v4: row-pair f32x2 packing (crossbar 75%) ----------------
// xw1[(b*T+t)][512] = h1[(t*B+b)][128] @ Wi1r + b1.  grid (GRIDX_H, 2).
// xs holds PLAIN floats (no duplication); weight scalars duplicated in registers.
__global__ void __launch_bounds__(256, 1) gemm_h_kernel(
    const float* __restrict__ X, const float* __restrict__ Wr,
    const float* __restrict__ bias, float* __restrict__ XW)
{
    extern __shared__ float sm[];
    float* Wsh = sm;                 // 128 k * 256 floats (cls half)
    float* xs  = sm + 128 * 256;     // 128 k * 32 rows plain floats = 16KB
    const int tid = threadIdx.x;
    const int cls = blockIdx.y;
    const int nl = tid & 63;         // n-unit within half
    const int rg = tid >> 6;         // row-group 0..3 (8 rows each)
    const int ng = cls * 64 + nl;    // global n-unit

    for (int i = tid; i < 128 * 64; i += 256) {
        int k = i >> 6, j4 = i & 63;
        ((float4*)Wsh)[i] = ((const float4*)Wr)[k * 128 + cls * 64 + j4];
    }
    float4 bv = ((const float4*)bias)[ng];
    const u64 bi = pack2(bv.x, bv.x), bf = pack2(bv.y, bv.y);
    const u64 bg = pack2(bv.z, bv.z), bo = pack2(bv.w, bv.w);

    // staging: sr = row-in-tile = lane (conflict-free), cq = warp picks 16 k
    const int sr = tid & 31, cq = tid >> 5;
    const float4* X4 = (const float4*)X;
    const float4* Wsh4 = (const float4*)Wsh;
    const ulonglong2* xs_u2 = (const ulonglong2*)xs;
    float4* XW4 = (float4*)XW;

    int tile = blockIdx.x;
    float4 px0, px1, px2, px3;
    {
        size_t mr = (size_t)tile * 32 + sr;
        px0 = X4[mr * 32 + cq * 4 + 0];
        px1 = X4[mr * 32 + cq * 4 + 1];
        px2 = X4[mr * 32 + cq * 4 + 2];
        px3 = X4[mr * 32 + cq * 4 + 3];
    }

    for (; tile < NT_H; tile += GRIDX_H) {
        // stage plain inputs: xs[k][sr]; k = cq*16 + j   (STS.32, lanes contiguous)
        {
            int k0 = cq * 16;
            xs[(k0 + 0)  * 32 + sr] = px0.x;
            xs[(k0 + 1)  * 32 + sr] = px0.y;
            xs[(k0 + 2)  * 32 + sr] = px0.z;
            xs[(k0 + 3)  * 32 + sr] = px0.w;
            xs[(k0 + 4)  * 32 + sr] = px1.x;
            xs[(k0 + 5)  * 32 + sr] = px1.y;
            xs[(k0 + 6)  * 32 + sr] = px1.z;
            xs[(k0 + 7)  * 32 + sr] = px1.w;
            xs[(k0 + 8)  * 32 + sr] = px2.x;
            xs[(k0 + 9)  * 32 + sr] = px2.y;
            xs[(k0 + 10) * 32 + sr] = px2.z;
            xs[(k0 + 11) * 32 + sr] = px2.w;
            xs[(k0 + 12) * 32 + sr] = px3.x;
            xs[(k0 + 13) * 32 + sr] = px3.y;
            xs[(k0 + 14) * 32 + sr] = px3.z;
            xs[(k0 + 15) * 32 + sr] = px3.w;
        }
        __syncthreads();

        int tn = tile + GRIDX_H;
        if (tn < NT_H) {
            size_t mr = (size_t)tn * 32 + sr;
            px0 = X4[mr * 32 + cq * 4 + 0];
            px1 = X4[mr * 32 + cq * 4 + 1];
            px2 = X4[mr * 32 + cq * 4 + 2];
            px3 = X4[mr * 32 + cq * 4 + 3];
        }

        // accumulators by row-pair: a<gate>[rp] = (row 2rp, row 2rp+1)
        u64 ai[4], af[4], ag[4], ao[4];
        #pragma unroll
        for (int j = 0; j < 4; j++) { ai[j] = bi; af[j] = bf; ag[j] = bg; ao[j] = bo; }

        #pragma unroll 8
        for (int k = 0; k < 128; k++) {
            float4 wv = Wsh4[k * 64 + nl];
            u64 wi = pack2(wv.x, wv.x), wf_ = pack2(wv.y, wv.y);
            u64 wg = pack2(wv.z, wv.z), wo = pack2(wv.w, wv.w);
            ulonglong2 hA = xs_u2[k * 8 + rg * 2];      // rows 8rg..+3
            ulonglong2 hB = xs_u2[k * 8 + rg * 2 + 1];  // rows 8rg+4..+7
            fma2(ai[0], wi, hA.x); fma2(af[0], wf_, hA.x); fma2(ag[0], wg, hA.x); fma2(ao[0], wo, hA.x);
            fma2(ai[1], wi, hA.y); fma2(af[1], wf_, hA.y); fma2(ag[1], wg, hA.y); fma2(ao[1], wo, hA.y);
            fma2(ai[2], wi, hB.x); fma2(af[2], wf_, hB.x); fma2(ag[2], wg, hB.x); fma2(ao[2], wo, hB.x);
            fma2(ai[3], wi, hB.y); fma2(af[3], wf_, hB.y); fma2(ag[3], wg, hB.y); fma2(ao[3], wo, hB.y);
        }

        // epilogue: 8 rows, scatter to [b*T+t] layout
        #pragma unroll
        for (int rp = 0; rp < 4; rp++) {
            float i0, i1, f0, f1, g0, g1, o0, o1;
            unpk(ai[rp], i0, i1); unpk(af[rp], f0, f1);
            unpk(ag[rp], g0, g1); unpk(ao[rp], o0, o1);
            int mh = tile * 32 + rg * 8 + 2 * rp;   // h1-order = t*B + b
            int b0_ = mh & 1023, t0_ = mh >> 10;
            XW4[((size_t)b0_ * TSTEPS + t0_) * 128 + ng] = make_float4(i0, f0, g0, o0);
            int mh1 = mh + 1;
            int b1_ = mh1 & 1023, t1_ = mh1 >> 10;
            XW4[((size_t)b1_ * TSTEPS + t1_) * 128 + ng] = make_float4(i1, f1, g1, o1);
        }
        __syncthreads();
    }
}

// ---------------- recurrence v5: row-pair f32x2 packing (crossbar 75%) ----------------
// 128 threads, thread owns hidden unit n = tid, 8 batch rows. h stored PLAIN.
// LAYER 0: hout = g_h1 [t*B+b][128]   LAYER 1: hout = g_last [b][128]
template <int LAYER>
__global__ void __launch_bounds__(128, 1) rec_kernel(
    const float* __restrict__ xw,   // [b*T+t][512], gate seeds incl. bias
    const float* __restrict__ Wr,   // [128][512] reordered
    float* __restrict__ hout)
{
    extern __shared__ float sm[];
    float* Wsh = sm;                 // KS*512 floats
    float* in2 = sm + KS * 512;      // 2 buffers x 128 n x 8 rows plain = 2048 floats
    const int tid = threadIdx.x;     // n-unit 0..127
    const int R0 = blockIdx.x * 8;

    for (int i = tid; i < KS * 128; i += 128)
        ((float4*)Wsh)[i] = ((const float4*)Wr)[i];

    float4 wreg[KR];                 // plain gate weights for reg-resident rows
    #pragma unroll
    for (int j = 0; j < KR; j++)
        wreg[j] = ((const float4*)Wr)[(KS + j) * 128 + tid];

    for (int i = tid; i < 512; i += 128)
        ((float4*)in2)[i] = make_float4(0.f, 0.f, 0.f, 0.f);
    __syncthreads();

    const float4* Wsh4 = (const float4*)Wsh;

    float cst[8];
    #pragma unroll
    for (int r = 0; r < 8; r++) cst[r] = 0.0f;

    const float4* xp = (const float4*)xw + ((size_t)R0 * TSTEPS) * 128 + tid;
    const size_t RS = (size_t)TSTEPS * 128;   // float4 stride per batch row

    for (int t = 0; t < TSTEPS; t++) {
        // prefetch gate seeds for all 8 rows (hidden by k-loop)
        float4 xg[8];
        #pragma unroll
        for (int r = 0; r < 8; r++)
            xg[r] = xp[(size_t)r * RS + (size_t)t * 128];

        // read buffer holds h(t-1) plain: per k, 8 floats = 2 ulonglong2
        const ulonglong2* rb = (const ulonglong2*)in2 + ((t + 1) & 1) * 256;
        float4* wb = (float4*)in2 + (t & 1) * 256;

        u64 ai[4], af[4], ag[4], ao[4];
        #pragma unroll
        for (int j = 0; j < 4; j++) { ai[j] = 0; af[j] = 0; ag[j] = 0; ao[j] = 0; }

        #pragma unroll 8
        for (int k = 0; k < KS; k++) {
            float4 wv = Wsh4[k * 128 + tid];
            u64 wi = pack2(wv.x, wv.x), wf_ = pack2(wv.y, wv.y);
            u64 wg = pack2(wv.z, wv.z), wo = pack2(wv.w, wv.w);
            ulonglong2 hA = rb[k * 2];       // rows 0..3
            ulonglong2 hB = rb[k * 2 + 1];   // rows 4..7
            fma2(ai[0], wi, hA.x); fma2(af[0], wf_, hA.x); fma2(ag[0], wg, hA.x); fma2(ao[0], wo, hA.x);
            fma2(ai[1], wi, hA.y); fma2(af[1], wf_, hA.y); fma2(ag[1], wg, hA.y); fma2(ao[1], wo, hA.y);
            fma2(ai[2], wi, hB.x); fma2(af[2], wf_, hB.x); fma2(ag[2], wg, hB.x); fma2(ao[2], wo, hB.x);
            fma2(ai[3], wi, hB.y); fma2(af[3], wf_, hB.y); fma2(ag[3], wg, hB.y); fma2(ao[3], wo, hB.y);
        }
        #pragma unroll
        for (int j = 0; j < KR; j++) {
            int k = KS + j;
            float4 wv = wreg[j];
            u64 wi = pack2(wv.x, wv.x), wf_ = pack2(wv.y, wv.y);
            u64 wg = pack2(wv.z, wv.z), wo = pack2(wv.w, wv.w);
            ulonglong2 hA = rb[k * 2];
            ulonglong2 hB = rb[k * 2 + 1];
            fma2(ai[0], wi, hA.x); fma2(af[0], wf_, hA.x); fma2(ag[0], wg, hA.x); fma2(ao[0], wo, hA.x);
            fma2(ai[1], wi, hA.y); fma2(af[1], wf_, hA.y); fma2(ag[1], wg, hA.y); fma2(ao[1], wo, hA.y);
            fma2(ai[2], wi, hB.x); fma2(af[2], wf_, hB.x); fma2(ag[2], wg, hB.x); fma2(ao[2], wo, hB.x);
            fma2(ai[3], wi, hB.y); fma2(af[3], wf_, hB.y); fma2(ag[3], wg, hB.y); fma2(ao[3], wo, hB.y);
        }

        float hv[8];
        #pragma unroll
        for (int rp = 0; rp < 4; rp++) {
            float i0, i1, f0, f1, g0, g1, o0, o1;
            unpk(ai[rp], i0, i1); unpk(af[rp], f0, f1);
            unpk(ag[rp], g0, g1); unpk(ao[rp], o0, o1);
            {
                int r = 2 * rp;
                float gi = i0 + xg[r].x, gf = f0 + xg[r].y;
                float gg = g0 + xg[r].z, go = o0 + xg[r].w;
                float iv = sigf(gi), fv = sigf(gf), gv = tanhf_(gg), ov = sigf(go);
                float cc = fv * cst[r] + iv * gv;
                cst[r] = cc;
                hv[r] = ov * tanhf_(cc);
            }
            {
                int r = 2 * rp + 1;
                float gi = i1 + xg[r].x, gf = f1 + xg[r].y;
                float gg = g1 + xg[r].z, go = o1 + xg[r].w;
                float iv = sigf(gi), fv = sigf(gf), gv = tanhf_(gg), ov = sigf(go);
                float cc = fv * cst[r] + iv * gv;
                cst[r] = cc;
                hv[r] = ov * tanhf_(cc);
            }
        }

        // publish h(t) plain: wb[n*2] = rows 0..3, wb[n*2+1] = rows 4..7
        wb[tid * 2 + 0] = make_float4(hv[0], hv[1], hv[2], hv[3]);
        wb[tid * 2 + 1] = make_float4(hv[4], hv[5], hv[6], hv[7]);

        if (LAYER == 0) {
            float* o = hout + ((size_t)t * BATCH + R0) * HID + tid;
            #pragma unroll
            for (int r = 0; r < 8; r++) o[r * HID] = hv[r];
        } else {
            if (t == TSTEPS - 1) {
                float* o = hout + (size_t)R0 * HID + tid;
                #pragma unroll
                for (int r = 0; r < 8; r++) o[r * HID] = hv[r];
            }
        }
        __syncthreads();   // h(t) visible before next step's k-loop
    }
}

// ---------------- batchnorm statistics ----------------
__global__ void bn_stats_kernel() {
    int n = blockIdx.x;
    int tid = threadIdx.x;
    float s = 0.f, ss = 0.f;
    for (int b = tid; b < BATCH; b += 256) {
        float v = g_last[(size_t)b * HID + n];
        s += v; ss += v * v;
    }
    __shared__ float sh1[256], sh2[256];
    sh1[tid] = s; sh2[tid] = ss;
    __syncthreads();
    for (int o = 128; o > 0; o >>= 1) {
        if (tid < o) { sh1[tid] += sh1[tid + o]; sh2[tid] += sh2[tid + o]; }
        __syncthreads();
    }
    if (tid == 0) {
        float mu = sh1[0] * (1.0f / BATCH);
        float var = sh2[0] * (1.0f / BATCH) - mu * mu;
        g_mu[n] = mu;
        g_rstd[n] = rsqrtf(var + 1e-5f);
    }
}

// ---------------- MLP head ----------------
__global__ void head_kernel(const float* __restrict__ gamma, const float* __restrict__ beta,
                            const float* __restrict__ W1, const float* __restrict__ b1,
                            const float* __restrict__ W2, const float* __restrict__ b2,
                            float* __restrict__ out) {
    __shared__ float w1sh[128 * 33];
    __shared__ float scale_sh[128], shift_sh[128];
    int tid = threadIdx.x;
    for (int i = tid; i < 32 * 128; i += 256) {
        int j = i >> 7, n = i & 127;
        w1sh[n * 33 + j] = W1[i];
    }
    for (int i = tid; i < 128; i += 256) {
        float rs = g_rstd[i] * gamma[i];
        scale_sh[i] = rs;
        shift_sh[i] = beta[i] - g_mu[i] * rs;
    }
    __syncthreads();
    int w = tid >> 5, lane = tid & 31;
    int b = blockIdx.x * 8 + w;
    const float* lrow = g_last + (size_t)b * HID;
    float z = b1[lane];
    #pragma unroll 4
    for (int n = 0; n < 128; n++) {
        float nv = fmaf(lrow[n], scale_sh[n], shift_sh[n]);
        z = fmaf(w1sh[n * 33 + lane], nv, z);
    }
    z = fmaxf(z, 0.0f);
    float acc = z * W2[lane];
    #pragma unroll
    for (int o = 16; o > 0; o >>= 1) acc += __shfl_down_sync(0xffffffffu, acc, o);
    if (lane == 0) out[b] = acc + b2[0];
}

// ---------------- launcher ----------------
extern "C" void kernel_launch(void* const* d_in, const int* in_sizes, int n_in,
                              void* d_out, int out_size) {
    (void)in_sizes; (void)n_in; (void)out_size;
    const float* x    = (const float*)d_in[0];
    const float* Wih0 = (const float*)d_in[1];
    const float* Whh0 = (const float*)d_in[2];
    const float* bih0 = (const float*)d_in[3];
    const float* bhh0 = (const float*)d_in[4];
    const float* Wih1 = (const float*)d_in[5];
    const float* Whh1 = (const float*)d_in[6];
    const float* bih1 = (const float*)d_in[7];
    const float* bhh1 = (const float*)d_in[8];
    const float* gamma = (const float*)d_in[9];
    const float* beta  = (const float*)d_in[10];
    const float* W1 = (const float*)d_in[11];
    const float* b1 = (const float*)d_in[12];
    const float* W2 = (const float*)d_in[13];
    const float* b2 = (const float*)d_in[14];
    float* out = (float*)d_out;

    float *p_Wr0, *p_Wr1, *p_Wi0r, *p_Wi1r, *p_b0r, *p_b1r, *p_xw, *p_h1, *p_last;
    cudaGetSymbolAddress((void**)&p_Wr0, g_Wr0);
    cudaGetSymbolAddress((void**)&p_Wr1, g_Wr1);
    cudaGetSymbolAddress((void**)&p_Wi0r, g_Wi0r);
    cudaGetSymbolAddress((void**)&p_Wi1r, g_Wi1r);
    cudaGetSymbolAddress((void**)&p_b0r, g_b0r);
    cudaGetSymbolAddress((void**)&p_b1r, g_b1r);
    cudaGetSymbolAddress((void**)&p_xw,  g_xw);
    cudaGetSymbolAddress((void**)&p_h1,  g_h1);
    cudaGetSymbolAddress((void**)&p_last, g_last);

    constexpr int SMR  = (KS * 512 + 2048) * 4;            // 221,184 B
    constexpr int SMG1 = (128 * 256 + 128 * 32) * 4;       // 147,456 B
    static bool attr_done = false;
    if (!attr_done) {
        cudaFuncSetAttribute(rec_kernel<0>, cudaFuncAttributeMaxDynamicSharedMemorySize, SMR);
        cudaFuncSetAttribute(rec_kernel<1>, cudaFuncAttributeMaxDynamicSharedMemorySize, SMR);
        cudaFuncSetAttribute(gemm_h_kernel, cudaFuncAttributeMaxDynamicSharedMemorySize, SMG1);
        attr_done = true;
    }

    prep_kernel<<<256, 256>>>(Wih0, Whh0, bih0, bhh0, Wih1, Whh1, bih1, bhh1);
    gemm_x_kernel<<<512, 256>>>(x, p_Wi0r, p_b0r, p_xw);                         // xw0
    rec_kernel<0><<<BATCH / 8, 128, SMR>>>(p_xw, p_Wr0, p_h1);                   // layer 0
    gemm_h_kernel<<<dim3(GRIDX_H, 2), 256, SMG1>>>(p_h1, p_Wi1r, p_b1r, p_xw);   // xw1
    rec_kernel<1><<<BATCH / 8, 128, SMR>>>(p_xw, p_Wr1, p_last);                 // layer 1
    bn_stats_kernel<<<HID, 256>>>();
    head_kernel<<<BATCH / 8, 256>>>(gamma, beta, W1, b1, W2, b2, out);
}